// round 2
// baseline (speedup 1.0000x reference)
#include <cuda_runtime.h>
#include <cuda_bf16.h>
#include <math.h>

// ---------------- problem-size maxima (fixed instance: T=4096,D=1024,F=4096,E=8,k=2)
#define T_MAX    4096
#define E_MAX    8
#define SLOT_MAX 2
#define D_MAX    1024
#define F_MAX    4096
// padded rows: T*k plus up to 127 pad per expert segment
#define RPAD_MAX (T_MAX * SLOT_MAX + E_MAX * 128)   // 9216
#define TILES_MAX (RPAD_MAX / 128)                  // 72

// ---------------- device scratch (static: no allocation anywhere)
__device__ float g_Xg[(size_t)RPAD_MAX * D_MAX];    // gathered tokens      36 MB
__device__ float g_H [(size_t)RPAD_MAX * F_MAX];    // hidden activations  151 MB
__device__ float g_O [(size_t)RPAD_MAX * D_MAX];    // expert outputs       36 MB
__device__ int   g_sel [T_MAX * SLOT_MAX];
__device__ float g_wts [T_MAX * SLOT_MAX];
__device__ int   g_pos [T_MAX * SLOT_MAX];
__device__ int   g_count [E_MAX];
__device__ int   g_cursor[E_MAX];
__device__ int   g_off   [E_MAX + 1];
__device__ int   g_tile2e[TILES_MAX];
__device__ int   g_row2tok[RPAD_MAX];

// ---------------- init: reset counters & maps
__global__ void k_init() {
    int i = blockIdx.x * blockDim.x + threadIdx.x;
    if (i < RPAD_MAX)  g_row2tok[i] = -1;
    if (i < TILES_MAX) g_tile2e[i]  = -1;
    if (i < E_MAX)   { g_count[i] = 0; g_cursor[i] = 0; }
}

// ---------------- router: logits -> softmax -> top-k -> renorm
__global__ void k_router(const float* __restrict__ x,
                         const float* __restrict__ gw,
                         const float* __restrict__ gb,
                         const int* __restrict__ topk_p,
                         int D, int E) {
    int t = blockIdx.x;
    float acc[E_MAX];
    #pragma unroll
    for (int e = 0; e < E_MAX; e++) acc[e] = 0.f;

    const float* xr = x + (size_t)t * D;
    for (int d = threadIdx.x; d < D; d += blockDim.x) {
        float xv = xr[d];
        for (int e = 0; e < E; e++) acc[e] += xv * gw[(size_t)e * D + d];
    }
    __shared__ float sred[E_MAX][8];
    int lane = threadIdx.x & 31, wid = threadIdx.x >> 5;
    for (int e = 0; e < E; e++) {
        float v = acc[e];
        #pragma unroll
        for (int o = 16; o > 0; o >>= 1) v += __shfl_down_sync(0xffffffffu, v, o);
        if (lane == 0) sred[e][wid] = v;
    }
    __syncthreads();
    if (threadIdx.x == 0) {
        int nw = blockDim.x >> 5;
        float logit[E_MAX];
        float mx = -1e30f;
        for (int e = 0; e < E; e++) {
            float s = gb[e];
            for (int w = 0; w < nw; w++) s += sred[e][w];
            logit[e] = s;
            mx = fmaxf(mx, s);
        }
        float p[E_MAX], Z = 0.f;
        for (int e = 0; e < E; e++) { p[e] = expf(logit[e] - mx); Z += p[e]; }
        float invZ = 1.f / Z;
        for (int e = 0; e < E; e++) p[e] *= invZ;

        int k = topk_p ? *topk_p : 2;
        if (k > SLOT_MAX) k = SLOT_MAX;
        if (k < 1) k = 1;
        bool used[E_MAX];
        for (int e = 0; e < E; e++) used[e] = false;
        float wsum = 0.f;
        int   sels[SLOT_MAX];
        float wv [SLOT_MAX];
        for (int s = 0; s < k; s++) {
            int best = 0; float bv = -1.f;
            for (int e = 0; e < E; e++)
                if (!used[e] && p[e] > bv) { bv = p[e]; best = e; }  // strict > => lowest index on tie
            used[best] = true;
            sels[s] = best; wv[s] = bv; wsum += bv;
            atomicAdd(&g_count[best], 1);
        }
        float inv = 1.f / wsum;
        for (int s = 0; s < k; s++) {
            g_sel[t * SLOT_MAX + s] = sels[s];
            g_wts[t * SLOT_MAX + s] = wv[s] * inv;
        }
        for (int s = k; s < SLOT_MAX; s++) {
            g_sel[t * SLOT_MAX + s] = -1;
            g_wts[t * SLOT_MAX + s] = 0.f;
        }
    }
}

// ---------------- scan: 128-aligned expert segment offsets + tile->expert map
__global__ void k_scan(int E) {
    if (threadIdx.x != 0 || blockIdx.x != 0) return;
    int off = 0;
    for (int e = 0; e < E; e++) {
        g_off[e] = off;
        int tiles = (g_count[e] + 127) >> 7;
        for (int i = 0; i < tiles; i++) g_tile2e[(off >> 7) + i] = e;
        off += tiles << 7;
    }
    g_off[E] = off;
}

// ---------------- assign: (token, slot) -> permuted row
__global__ void k_assign(int T) {
    int idx = blockIdx.x * blockDim.x + threadIdx.x;
    if (idx >= T * SLOT_MAX) return;
    int t = idx / SLOT_MAX, s = idx % SLOT_MAX;
    int e = g_sel[t * SLOT_MAX + s];
    if (e < 0) { g_pos[t * SLOT_MAX + s] = -1; return; }
    int pos = atomicAdd(&g_cursor[e], 1);
    int row = g_off[e] + pos;
    g_row2tok[row] = t;
    g_pos[t * SLOT_MAX + s] = row;
}

// ---------------- gather: Xg[row] = x[token]  (zeros for pad rows)
__global__ void k_gather(const float* __restrict__ x, int D) {
    int row = blockIdx.x;
    int tok = g_row2tok[row];
    float4* dst = (float4*)(g_Xg + (size_t)row * D);
    if (tok >= 0) {
        const float4* src = (const float4*)(x + (size_t)tok * D);
        for (int c = threadIdx.x; c < (D >> 2); c += blockDim.x) dst[c] = src[c];
    } else {
        float4 z = make_float4(0.f, 0.f, 0.f, 0.f);
        for (int c = threadIdx.x; c < (D >> 2); c += blockDim.x) dst[c] = z;
    }
}

// ---------------- GEMM: C[128x128 tile] = act(A @ W[e] + bias[e])
// A: [rows, K] row-major (row base = tile_m*128), W: [E, K, N] row-major,
// bias: [E, N], C row stride = N. act=1 -> SiLU.
__global__ void __launch_bounds__(256)
k_gemm(const float* __restrict__ Abase, const float* __restrict__ Wall,
       const float* __restrict__ Ball, float* __restrict__ C,
       int N, int K, int act) {
    int tile_m = blockIdx.y, tile_n = blockIdx.x;
    int e = g_tile2e[tile_m];
    if (e < 0) return;

    const float* A    = Abase + (size_t)tile_m * 128 * K;
    const float* B    = Wall  + (size_t)e * K * N + (size_t)tile_n * 128;
    const float* bias = Ball  + (size_t)e * N + (size_t)tile_n * 128;
    float*       Cb   = C     + (size_t)tile_m * 128 * N + (size_t)tile_n * 128;

    __shared__ float As[16][132];   // padded: store-transposed A
    __shared__ float Bs[16][128];

    float accu[8][8];
    #pragma unroll
    for (int i = 0; i < 8; i++)
        #pragma unroll
        for (int j = 0; j < 8; j++) accu[i][j] = 0.f;

    int tid = threadIdx.x;
    int tx = tid & 15, ty = tid >> 4;   // tx: n-octet, ty: m-octet

    for (int k0 = 0; k0 < K; k0 += 16) {
        #pragma unroll
        for (int l = 0; l < 2; l++) {
            int q  = tid + l * 256;
            int ar = q >> 2, ak = (q & 3) << 2;
            float4 av = *(const float4*)(A + (size_t)ar * K + k0 + ak);
            As[ak + 0][ar] = av.x; As[ak + 1][ar] = av.y;
            As[ak + 2][ar] = av.z; As[ak + 3][ar] = av.w;
            int bk = q >> 5, bc = (q & 31) << 2;
            *(float4*)&Bs[bk][bc] = *(const float4*)(B + (size_t)(k0 + bk) * N + bc);
        }
        __syncthreads();
        #pragma unroll
        for (int kk = 0; kk < 16; kk++) {
            float ra[8], rb[8];
            #pragma unroll
            for (int i = 0; i < 8; i++) ra[i] = As[kk][ty * 8 + i];
            #pragma unroll
            for (int j = 0; j < 8; j++) rb[j] = Bs[kk][tx * 8 + j];
            #pragma unroll
            for (int i = 0; i < 8; i++)
                #pragma unroll
                for (int j = 0; j < 8; j++) accu[i][j] = fmaf(ra[i], rb[j], accu[i][j]);
        }
        __syncthreads();
    }
    #pragma unroll
    for (int i = 0; i < 8; i++) {
        int m = ty * 8 + i;
        #pragma unroll
        for (int j = 0; j < 8; j++) {
            int n = tx * 8 + j;
            float v = accu[i][j] + bias[n];
            if (act) v = v / (1.f + expf(-v));   // SiLU
            Cb[(size_t)m * N + n] = v;
        }
    }
}

// ---------------- combine: out[t] = sum_s w_s * O[row_s]
__global__ void k_combine(float* __restrict__ out, int D) {
    int t = blockIdx.x;
    int   rows[SLOT_MAX];
    float ws  [SLOT_MAX];
    #pragma unroll
    for (int s = 0; s < SLOT_MAX; s++) {
        rows[s] = g_pos[t * SLOT_MAX + s];
        ws[s]   = g_wts[t * SLOT_MAX + s];
    }
    float4* dst = (float4*)(out + (size_t)t * D);
    for (int c = threadIdx.x; c < (D >> 2); c += blockDim.x) {
        float4 a = make_float4(0.f, 0.f, 0.f, 0.f);
        #pragma unroll
        for (int s = 0; s < SLOT_MAX; s++) {
            if (rows[s] < 0) continue;
            const float4 v = ((const float4*)(g_O + (size_t)rows[s] * D))[c];
            a.x = fmaf(ws[s], v.x, a.x); a.y = fmaf(ws[s], v.y, a.y);
            a.z = fmaf(ws[s], v.z, a.z); a.w = fmaf(ws[s], v.w, a.w);
        }
        dst[c] = a;
    }
}

// ---------------- launch
extern "C" void kernel_launch(void* const* d_in, const int* in_sizes, int n_in,
                              void* d_out, int out_size) {
    const float* x    = (const float*)d_in[0];
    const float* gw   = (const float*)d_in[1];
    const float* gb   = (const float*)d_in[2];
    const float* w1   = (const float*)d_in[3];
    const float* b1   = (const float*)d_in[4];
    const float* w2   = (const float*)d_in[5];
    const float* b2   = (const float*)d_in[6];
    const int*   topk = (n_in > 7) ? (const int*)d_in[7] : nullptr;
    float* out = (float*)d_out;

    const int E = in_sizes[2];                 // gate_b
    const int D = in_sizes[1] / E;             // gate_w = [E, D]
    const int F = in_sizes[4] / E;             // b1 = [E, F]
    const int T = in_sizes[0] / D;             // x = [T, D]

    // Resolve REAL device addresses of the __device__ scratch (host-side
    // symbol names are shadow variables — passing them as kernel args is the
    // R1 bug). cudaGetSymbolAddress is a pure query: capture-safe, no alloc.
    float *Xg = nullptr, *H = nullptr, *O = nullptr;
    cudaGetSymbolAddress((void**)&Xg, g_Xg);
    cudaGetSymbolAddress((void**)&H,  g_H);
    cudaGetSymbolAddress((void**)&O,  g_O);

    k_init<<<(RPAD_MAX + 255) / 256, 256>>>();
    k_router<<<T, 256>>>(x, gw, gb, topk, D, E);
    k_scan<<<1, 32>>>(E);
    k_assign<<<(T * SLOT_MAX + 255) / 256, 256>>>(T);
    k_gather<<<RPAD_MAX, 256>>>(x, D);

    dim3 g1(F / 128, TILES_MAX);
    k_gemm<<<g1, 256>>>(Xg, w1, b1, H, F, D, 1);   // H = silu(Xg @ w1 + b1)
    dim3 g2(D / 128, TILES_MAX);
    k_gemm<<<g2, 256>>>(H, w2, b2, O, D, F, 0);    // O = H @ w2 + b2

    k_combine<<<T, 256>>>(out, D);
}

// round 4
// speedup vs baseline: 2.0539x; 2.0539x over previous
#include <cuda_runtime.h>
#include <cuda_bf16.h>
#include <math.h>
#include <stdint.h>

// ---------------- problem-size maxima (fixed instance: T=4096,D=1024,F=4096,E=8,k=2)
#define T_MAX    4096
#define E_MAX    8
#define SLOT_MAX 2
#define D_MAX    1024
#define F_MAX    4096
#define RPAD_MAX (T_MAX * SLOT_MAX + E_MAX * 128)   // 9216
#define TILES_MAX (RPAD_MAX / 128)                  // 72

// ---------------- device scratch (static: no allocation anywhere)
__device__ float g_Xg [(size_t)RPAD_MAX * D_MAX];           // gathered tokens (tf32-rounded)
__device__ float g_H  [(size_t)RPAD_MAX * F_MAX];           // hidden (tf32-rounded)
__device__ float g_O  [(size_t)RPAD_MAX * D_MAX];           // expert outputs (fp32)
__device__ float g_W1t[(size_t)E_MAX * F_MAX * D_MAX];      // w1^T  [E][F][D] tf32-rounded
__device__ float g_W2t[(size_t)E_MAX * D_MAX * F_MAX];      // w2^T  [E][D][F] tf32-rounded
__device__ int   g_sel [T_MAX * SLOT_MAX];
__device__ float g_wts [T_MAX * SLOT_MAX];
__device__ int   g_pos [T_MAX * SLOT_MAX];
__device__ int   g_count [E_MAX];
__device__ int   g_cursor[E_MAX];
__device__ int   g_off   [E_MAX + 1];
__device__ int   g_tile2e[TILES_MAX];
__device__ int   g_row2tok[RPAD_MAX];

// ---------------- helpers ----------------
__device__ __forceinline__ float tf32r(float x) {   // round-to-nearest tf32 (low 13 bits zero)
    uint32_t u;
    asm("cvt.rna.tf32.f32 %0, %1;" : "=r"(u) : "f"(x));
    return __uint_as_float(u);
}

// warp-level tensor op, baseline target (compiles for compute_103, runs as HMMA)
__device__ __forceinline__ void mma16n8k8(float c[4],
                                          uint32_t a0, uint32_t a1, uint32_t a2, uint32_t a3,
                                          uint32_t b0, uint32_t b1) {
    asm volatile(
        "mma.sync.aligned.m16n8k8.row.col.f32.tf32.tf32.f32 "
        "{%0,%1,%2,%3}, {%4,%5,%6,%7}, {%8,%9}, {%0,%1,%2,%3};"
        : "+f"(c[0]), "+f"(c[1]), "+f"(c[2]), "+f"(c[3])
        : "r"(a0), "r"(a1), "r"(a2), "r"(a3), "r"(b0), "r"(b1));
}

// ---------------- init ----------------
__global__ void k_init() {
    int i = blockIdx.x * blockDim.x + threadIdx.x;
    if (i < RPAD_MAX)  g_row2tok[i] = -1;
    if (i < TILES_MAX) g_tile2e[i]  = -1;
    if (i < E_MAX)   { g_count[i] = 0; g_cursor[i] = 0; }
}

// ---------------- router ----------------
__global__ void k_router(const float* __restrict__ x, const float* __restrict__ gw,
                         const float* __restrict__ gb, const int* __restrict__ topk_p,
                         int D, int E) {
    int t = blockIdx.x;
    float acc[E_MAX];
    #pragma unroll
    for (int e = 0; e < E_MAX; e++) acc[e] = 0.f;
    const float* xr = x + (size_t)t * D;
    for (int d = threadIdx.x; d < D; d += blockDim.x) {
        float xv = xr[d];
        for (int e = 0; e < E; e++) acc[e] += xv * gw[(size_t)e * D + d];
    }
    __shared__ float sred[E_MAX][8];
    int lane = threadIdx.x & 31, wid = threadIdx.x >> 5;
    for (int e = 0; e < E; e++) {
        float v = acc[e];
        #pragma unroll
        for (int o = 16; o > 0; o >>= 1) v += __shfl_down_sync(0xffffffffu, v, o);
        if (lane == 0) sred[e][wid] = v;
    }
    __syncthreads();
    if (threadIdx.x == 0) {
        int nw = blockDim.x >> 5;
        float logit[E_MAX], mx = -1e30f;
        for (int e = 0; e < E; e++) {
            float s = gb[e];
            for (int w = 0; w < nw; w++) s += sred[e][w];
            logit[e] = s; mx = fmaxf(mx, s);
        }
        float p[E_MAX], Z = 0.f;
        for (int e = 0; e < E; e++) { p[e] = expf(logit[e] - mx); Z += p[e]; }
        float invZ = 1.f / Z;
        for (int e = 0; e < E; e++) p[e] *= invZ;

        int k = topk_p ? *topk_p : 2;
        if (k > SLOT_MAX) k = SLOT_MAX;
        if (k < 1) k = 1;
        bool used[E_MAX];
        for (int e = 0; e < E; e++) used[e] = false;
        float wsum = 0.f;
        int sels[SLOT_MAX]; float wv[SLOT_MAX];
        for (int s = 0; s < k; s++) {
            int best = 0; float bv = -1.f;
            for (int e = 0; e < E; e++)
                if (!used[e] && p[e] > bv) { bv = p[e]; best = e; }  // strict > => lowest idx on tie
            used[best] = true;
            sels[s] = best; wv[s] = bv; wsum += bv;
            atomicAdd(&g_count[best], 1);
        }
        float inv = 1.f / wsum;
        for (int s = 0; s < k; s++) { g_sel[t*SLOT_MAX+s] = sels[s]; g_wts[t*SLOT_MAX+s] = wv[s]*inv; }
        for (int s = k; s < SLOT_MAX; s++) { g_sel[t*SLOT_MAX+s] = -1; g_wts[t*SLOT_MAX+s] = 0.f; }
    }
}

// ---------------- scan ----------------
__global__ void k_scan(int E) {
    if (threadIdx.x != 0 || blockIdx.x != 0) return;
    int off = 0;
    for (int e = 0; e < E; e++) {
        g_off[e] = off;
        int tiles = (g_count[e] + 127) >> 7;
        for (int i = 0; i < tiles; i++) g_tile2e[(off >> 7) + i] = e;
        off += tiles << 7;
    }
    g_off[E] = off;
}

// ---------------- assign ----------------
__global__ void k_assign(int T) {
    int idx = blockIdx.x * blockDim.x + threadIdx.x;
    if (idx >= T * SLOT_MAX) return;
    int t = idx / SLOT_MAX, s = idx % SLOT_MAX;
    int e = g_sel[t * SLOT_MAX + s];
    if (e < 0) { g_pos[t * SLOT_MAX + s] = -1; return; }
    int pos = atomicAdd(&g_cursor[e], 1);
    int row = g_off[e] + pos;
    g_row2tok[row] = t;
    g_pos[t * SLOT_MAX + s] = row;
}

// ---------------- gather (+ tf32 rna rounding) ----------------
__global__ void k_gather(const float* __restrict__ x, int D) {
    int row = blockIdx.x;
    int tok = g_row2tok[row];
    float4* dst = (float4*)(g_Xg + (size_t)row * D);
    if (tok >= 0) {
        const float4* src = (const float4*)(x + (size_t)tok * D);
        for (int c = threadIdx.x; c < (D >> 2); c += blockDim.x) {
            float4 v = src[c];
            v.x = tf32r(v.x); v.y = tf32r(v.y); v.z = tf32r(v.z); v.w = tf32r(v.w);
            dst[c] = v;
        }
    } else {
        float4 z = make_float4(0.f, 0.f, 0.f, 0.f);
        for (int c = threadIdx.x; c < (D >> 2); c += blockDim.x) dst[c] = z;
    }
}

// ---------------- weight convert + transpose: W[E][K][N] -> Wt[E][N][K], rna ----------------
__global__ void k_wconv(const float* __restrict__ W, float* __restrict__ Wt, int K, int N) {
    __shared__ float t[32][33];
    int e = blockIdx.z;
    const float* We = W + (size_t)e * K * N;
    float* Wte = Wt + (size_t)e * N * K;
    int n0 = blockIdx.x * 32, k0 = blockIdx.y * 32;
    #pragma unroll
    for (int i = 0; i < 32; i += 8) {
        int k = k0 + threadIdx.y + i;
        t[threadIdx.y + i][threadIdx.x] = tf32r(We[(size_t)k * N + n0 + threadIdx.x]);
    }
    __syncthreads();
    #pragma unroll
    for (int i = 0; i < 32; i += 8) {
        int n = n0 + threadIdx.y + i;
        Wte[(size_t)n * K + k0 + threadIdx.x] = t[threadIdx.x][threadIdx.y + i];
    }
}

// ---------------- tf32 tensor GEMM: C[128x128 tile] = act(A @ Wt[e]^T + bias[e]) ----------------
// A: [rows,K] row-major (K-contig), Wt: [E][Ntot][K] (K-contig), bias: [E][Ntot],
// C row stride = Ntot. act=1 -> SiLU + tf32 rna re-round (C feeds next GEMM's A).
#define BK 16
#define AS_STRIDE 136     // conflict-free A-fragment loads (136 % 32 == 8)
#define BS_STRIDE 20      // conflict-free B-fragment loads; 80B row => float4-aligned

__global__ void __launch_bounds__(256)
k_gemm_mma(const float* __restrict__ Abase, const float* __restrict__ Wt,
           const float* __restrict__ Ball, float* __restrict__ C,
           int Ntot, int K, int act) {
    int tile_m = blockIdx.y, tile_n = blockIdx.x;
    int e = g_tile2e[tile_m];
    if (e < 0) return;

    const float* A = Abase + (size_t)tile_m * 128 * K;
    const float* B = Wt + (size_t)e * Ntot * K + (size_t)tile_n * 128 * K;

    __shared__ uint32_t As[BK][AS_STRIDE];      // [k][m] transposed
    __shared__ uint32_t Bs[128][BS_STRIDE];     // [n][k]

    int tid = threadIdx.x, lane = tid & 31, wid = tid >> 5;
    int wm = wid & 1, wn = wid >> 1;            // warp tile: 64(m) x 32(n)
    int grp = lane >> 2, thr = lane & 3;

    float acc[4][4][4];
    #pragma unroll
    for (int mf = 0; mf < 4; mf++)
        #pragma unroll
        for (int nf = 0; nf < 4; nf++)
            #pragma unroll
            for (int c = 0; c < 4; c++) acc[mf][nf][c] = 0.f;

    for (int k0 = 0; k0 < K; k0 += BK) {
        // stage A (128x16, transposed) and B (128x16) — 512 float4 each
        #pragma unroll
        for (int l = 0; l < 2; l++) {
            int q = tid + l * 256;
            int ar = q >> 2, ak = (q & 3) << 2;
            float4 av = *(const float4*)(A + (size_t)ar * K + k0 + ak);
            As[ak + 0][ar] = __float_as_uint(av.x);
            As[ak + 1][ar] = __float_as_uint(av.y);
            As[ak + 2][ar] = __float_as_uint(av.z);
            As[ak + 3][ar] = __float_as_uint(av.w);
            int bn = q >> 2, bk = (q & 3) << 2;
            float4 bv = *(const float4*)(B + (size_t)bn * K + k0 + bk);
            *(float4*)&Bs[bn][bk] = bv;
        }
        __syncthreads();

        #pragma unroll
        for (int ks = 0; ks < BK; ks += 8) {
            uint32_t af[4][4], bf[4][2];
            #pragma unroll
            for (int mf = 0; mf < 4; mf++) {
                int m0 = wm * 64 + mf * 16;
                af[mf][0] = As[ks + thr    ][m0 + grp    ];
                af[mf][1] = As[ks + thr    ][m0 + grp + 8];
                af[mf][2] = As[ks + thr + 4][m0 + grp    ];
                af[mf][3] = As[ks + thr + 4][m0 + grp + 8];
            }
            #pragma unroll
            for (int nf = 0; nf < 4; nf++) {
                int n0 = wn * 32 + nf * 8;
                bf[nf][0] = Bs[n0 + grp][ks + thr    ];
                bf[nf][1] = Bs[n0 + grp][ks + thr + 4];
            }
            #pragma unroll
            for (int mf = 0; mf < 4; mf++)
                #pragma unroll
                for (int nf = 0; nf < 4; nf++)
                    mma16n8k8(acc[mf][nf], af[mf][0], af[mf][1], af[mf][2], af[mf][3],
                              bf[nf][0], bf[nf][1]);
        }
        __syncthreads();
    }

    // epilogue: bias (+ SiLU + rna), direct float2 stores
    const float* bias = Ball + (size_t)e * Ntot + (size_t)tile_n * 128;
    float* Cb = C + (size_t)tile_m * 128 * Ntot + (size_t)tile_n * 128;
    #pragma unroll
    for (int mf = 0; mf < 4; mf++) {
        #pragma unroll
        for (int nf = 0; nf < 4; nf++) {
            int row = wm * 64 + mf * 16 + grp;
            int col = wn * 32 + nf * 8 + thr * 2;
            float b0 = bias[col], b1 = bias[col + 1];
            float v00 = acc[mf][nf][0] + b0, v01 = acc[mf][nf][1] + b1;
            float v10 = acc[mf][nf][2] + b0, v11 = acc[mf][nf][3] + b1;
            if (act) {
                v00 = tf32r(v00 / (1.f + __expf(-v00)));
                v01 = tf32r(v01 / (1.f + __expf(-v01)));
                v10 = tf32r(v10 / (1.f + __expf(-v10)));
                v11 = tf32r(v11 / (1.f + __expf(-v11)));
            }
            *(float2*)(Cb + (size_t)row * Ntot + col)       = make_float2(v00, v01);
            *(float2*)(Cb + (size_t)(row + 8) * Ntot + col) = make_float2(v10, v11);
        }
    }
}

// ---------------- combine ----------------
__global__ void k_combine(float* __restrict__ out, int D) {
    int t = blockIdx.x;
    int rows[SLOT_MAX]; float ws[SLOT_MAX];
    #pragma unroll
    for (int s = 0; s < SLOT_MAX; s++) { rows[s] = g_pos[t*SLOT_MAX+s]; ws[s] = g_wts[t*SLOT_MAX+s]; }
    float4* dst = (float4*)(out + (size_t)t * D);
    for (int c = threadIdx.x; c < (D >> 2); c += blockDim.x) {
        float4 a = make_float4(0.f, 0.f, 0.f, 0.f);
        #pragma unroll
        for (int s = 0; s < SLOT_MAX; s++) {
            if (rows[s] < 0) continue;
            const float4 v = ((const float4*)(g_O + (size_t)rows[s] * D))[c];
            a.x = fmaf(ws[s], v.x, a.x); a.y = fmaf(ws[s], v.y, a.y);
            a.z = fmaf(ws[s], v.z, a.z); a.w = fmaf(ws[s], v.w, a.w);
        }
        dst[c] = a;
    }
}

// ---------------- launch ----------------
extern "C" void kernel_launch(void* const* d_in, const int* in_sizes, int n_in,
                              void* d_out, int out_size) {
    const float* x    = (const float*)d_in[0];
    const float* gw   = (const float*)d_in[1];
    const float* gb   = (const float*)d_in[2];
    const float* w1   = (const float*)d_in[3];
    const float* b1   = (const float*)d_in[4];
    const float* w2   = (const float*)d_in[5];
    const float* b2   = (const float*)d_in[6];
    const int*   topk = (n_in > 7) ? (const int*)d_in[7] : nullptr;
    float* out = (float*)d_out;

    const int E = in_sizes[2];
    const int D = in_sizes[1] / E;
    const int F = in_sizes[4] / E;
    const int T = in_sizes[0] / D;

    float *Xg = nullptr, *H = nullptr, *O = nullptr, *W1t = nullptr, *W2t = nullptr;
    cudaGetSymbolAddress((void**)&Xg,  g_Xg);
    cudaGetSymbolAddress((void**)&H,   g_H);
    cudaGetSymbolAddress((void**)&O,   g_O);
    cudaGetSymbolAddress((void**)&W1t, g_W1t);
    cudaGetSymbolAddress((void**)&W2t, g_W2t);

    k_init<<<(RPAD_MAX + 255) / 256, 256>>>();
    k_router<<<T, 256>>>(x, gw, gb, topk, D, E);
    k_scan<<<1, 32>>>(E);
    k_assign<<<(T * SLOT_MAX + 255) / 256, 256>>>(T);
    k_gather<<<RPAD_MAX, 256>>>(x, D);

    dim3 bt(32, 8);
    k_wconv<<<dim3(F / 32, D / 32, E), bt>>>(w1, W1t, D, F);   // [E][D][F] -> [E][F][D]
    k_wconv<<<dim3(D / 32, F / 32, E), bt>>>(w2, W2t, F, D);   // [E][F][D] -> [E][D][F]

    k_gemm_mma<<<dim3(F / 128, TILES_MAX), 256>>>(Xg, W1t, b1, H, F, D, 1);
    k_gemm_mma<<<dim3(D / 128, TILES_MAX), 256>>>(H, W2t, b2, O, D, F, 0);

    k_combine<<<T, 256>>>(out, D);
}

// round 5
// speedup vs baseline: 2.3741x; 1.1559x over previous
#include <cuda_runtime.h>
#include <cuda_bf16.h>
#include <math.h>
#include <stdint.h>

// ---------------- problem-size maxima (fixed instance: T=4096,D=1024,F=4096,E=8,k=2)
#define T_MAX    4096
#define E_MAX    8
#define SLOT_MAX 2
#define D_MAX    1024
#define F_MAX    4096
#define RPAD_MAX (T_MAX * SLOT_MAX + E_MAX * 128)   // 9216
#define TILES_MAX (RPAD_MAX / 128)                  // 72

// ---------------- device scratch (static: no allocation anywhere)
__device__ float g_Xg [(size_t)RPAD_MAX * D_MAX];           // gathered tokens (tf32-rounded)
__device__ float g_H  [(size_t)RPAD_MAX * F_MAX];           // hidden (tf32-rounded)
__device__ float g_O  [(size_t)RPAD_MAX * D_MAX];           // expert outputs (fp32)
__device__ float g_W1t[(size_t)E_MAX * F_MAX * D_MAX];      // w1^T  [E][F][D] tf32-rounded
__device__ float g_W2t[(size_t)E_MAX * D_MAX * F_MAX];      // w2^T  [E][D][F] tf32-rounded
__device__ int   g_sel [T_MAX * SLOT_MAX];
__device__ float g_wts [T_MAX * SLOT_MAX];
__device__ int   g_pos [T_MAX * SLOT_MAX];
__device__ int   g_count [E_MAX];
__device__ int   g_cursor[E_MAX];
__device__ int   g_off   [E_MAX + 1];
__device__ int   g_tile2e[TILES_MAX];
__device__ int   g_row2tok[RPAD_MAX];

// ---------------- helpers ----------------
__device__ __forceinline__ float tf32r(float x) {   // round-to-nearest tf32
    uint32_t u;
    asm("cvt.rna.tf32.f32 %0, %1;" : "=r"(u) : "f"(x));
    return __uint_as_float(u);
}
__device__ __forceinline__ uint32_t smem_u32(const void* p) {
    uint32_t a;
    asm("{ .reg .u64 t; cvta.to.shared.u64 t, %1; cvt.u32.u64 %0, t; }" : "=r"(a) : "l"(p));
    return a;
}
__device__ __forceinline__ void cp16(uint32_t dst, const void* src) {
    asm volatile("cp.async.cg.shared.global [%0], [%1], 16;" :: "r"(dst), "l"(src));
}
#define CP_COMMIT() asm volatile("cp.async.commit_group;" ::: "memory")
#define CP_WAIT1()  asm volatile("cp.async.wait_group 1;" ::: "memory")

// warp-level tensor op, baseline target (compiles for compute_103, runs on tensor pipe)
__device__ __forceinline__ void mma16n8k8(float c[4],
                                          uint32_t a0, uint32_t a1, uint32_t a2, uint32_t a3,
                                          uint32_t b0, uint32_t b1) {
    asm volatile(
        "mma.sync.aligned.m16n8k8.row.col.f32.tf32.tf32.f32 "
        "{%0,%1,%2,%3}, {%4,%5,%6,%7}, {%8,%9}, {%0,%1,%2,%3};"
        : "+f"(c[0]), "+f"(c[1]), "+f"(c[2]), "+f"(c[3])
        : "r"(a0), "r"(a1), "r"(a2), "r"(a3), "r"(b0), "r"(b1));
}

// ---------------- init ----------------
__global__ void k_init() {
    int i = blockIdx.x * blockDim.x + threadIdx.x;
    if (i < RPAD_MAX)  g_row2tok[i] = -1;
    if (i < TILES_MAX) g_tile2e[i]  = -1;
    if (i < E_MAX)   { g_count[i] = 0; g_cursor[i] = 0; }
}

// ---------------- router ----------------
__global__ void k_router(const float* __restrict__ x, const float* __restrict__ gw,
                         const float* __restrict__ gb, const int* __restrict__ topk_p,
                         int D, int E) {
    int t = blockIdx.x;
    float acc[E_MAX];
    #pragma unroll
    for (int e = 0; e < E_MAX; e++) acc[e] = 0.f;
    const float* xr = x + (size_t)t * D;
    for (int d = threadIdx.x; d < D; d += blockDim.x) {
        float xv = xr[d];
        for (int e = 0; e < E; e++) acc[e] += xv * gw[(size_t)e * D + d];
    }
    __shared__ float sred[E_MAX][8];
    int lane = threadIdx.x & 31, wid = threadIdx.x >> 5;
    for (int e = 0; e < E; e++) {
        float v = acc[e];
        #pragma unroll
        for (int o = 16; o > 0; o >>= 1) v += __shfl_down_sync(0xffffffffu, v, o);
        if (lane == 0) sred[e][wid] = v;
    }
    __syncthreads();
    if (threadIdx.x == 0) {
        int nw = blockDim.x >> 5;
        float logit[E_MAX], mx = -1e30f;
        for (int e = 0; e < E; e++) {
            float s = gb[e];
            for (int w = 0; w < nw; w++) s += sred[e][w];
            logit[e] = s; mx = fmaxf(mx, s);
        }
        float p[E_MAX], Z = 0.f;
        for (int e = 0; e < E; e++) { p[e] = expf(logit[e] - mx); Z += p[e]; }
        float invZ = 1.f / Z;
        for (int e = 0; e < E; e++) p[e] *= invZ;

        int k = topk_p ? *topk_p : 2;
        if (k > SLOT_MAX) k = SLOT_MAX;
        if (k < 1) k = 1;
        bool used[E_MAX];
        for (int e = 0; e < E; e++) used[e] = false;
        float wsum = 0.f;
        int sels[SLOT_MAX]; float wv[SLOT_MAX];
        for (int s = 0; s < k; s++) {
            int best = 0; float bv = -1.f;
            for (int e = 0; e < E; e++)
                if (!used[e] && p[e] > bv) { bv = p[e]; best = e; }  // strict > => lowest idx on tie
            used[best] = true;
            sels[s] = best; wv[s] = bv; wsum += bv;
            atomicAdd(&g_count[best], 1);
        }
        float inv = 1.f / wsum;
        for (int s = 0; s < k; s++) { g_sel[t*SLOT_MAX+s] = sels[s]; g_wts[t*SLOT_MAX+s] = wv[s]*inv; }
        for (int s = k; s < SLOT_MAX; s++) { g_sel[t*SLOT_MAX+s] = -1; g_wts[t*SLOT_MAX+s] = 0.f; }
    }
}

// ---------------- scan ----------------
__global__ void k_scan(int E) {
    if (threadIdx.x != 0 || blockIdx.x != 0) return;
    int off = 0;
    for (int e = 0; e < E; e++) {
        g_off[e] = off;
        int tiles = (g_count[e] + 127) >> 7;
        for (int i = 0; i < tiles; i++) g_tile2e[(off >> 7) + i] = e;
        off += tiles << 7;
    }
    g_off[E] = off;
}

// ---------------- assign ----------------
__global__ void k_assign(int T) {
    int idx = blockIdx.x * blockDim.x + threadIdx.x;
    if (idx >= T * SLOT_MAX) return;
    int t = idx / SLOT_MAX, s = idx % SLOT_MAX;
    int e = g_sel[t * SLOT_MAX + s];
    if (e < 0) { g_pos[t * SLOT_MAX + s] = -1; return; }
    int pos = atomicAdd(&g_cursor[e], 1);
    int row = g_off[e] + pos;
    g_row2tok[row] = t;
    g_pos[t * SLOT_MAX + s] = row;
}

// ---------------- gather (+ tf32 rna rounding) ----------------
__global__ void k_gather(const float* __restrict__ x, int D) {
    int row = blockIdx.x;
    int tok = g_row2tok[row];
    float4* dst = (float4*)(g_Xg + (size_t)row * D);
    if (tok >= 0) {
        const float4* src = (const float4*)(x + (size_t)tok * D);
        for (int c = threadIdx.x; c < (D >> 2); c += blockDim.x) {
            float4 v = src[c];
            v.x = tf32r(v.x); v.y = tf32r(v.y); v.z = tf32r(v.z); v.w = tf32r(v.w);
            dst[c] = v;
        }
    } else {
        float4 z = make_float4(0.f, 0.f, 0.f, 0.f);
        for (int c = threadIdx.x; c < (D >> 2); c += blockDim.x) dst[c] = z;
    }
}

// ---------------- weight convert + transpose: W[E][K][N] -> Wt[E][N][K], rna ----------------
__global__ void k_wconv(const float* __restrict__ W, float* __restrict__ Wt, int K, int N) {
    __shared__ float t[32][33];
    int e = blockIdx.z;
    const float* We = W + (size_t)e * K * N;
    float* Wte = Wt + (size_t)e * N * K;
    int n0 = blockIdx.x * 32, k0 = blockIdx.y * 32;
    #pragma unroll
    for (int i = 0; i < 32; i += 8) {
        int k = k0 + threadIdx.y + i;
        t[threadIdx.y + i][threadIdx.x] = tf32r(We[(size_t)k * N + n0 + threadIdx.x]);
    }
    __syncthreads();
    #pragma unroll
    for (int i = 0; i < 32; i += 8) {
        int n = n0 + threadIdx.y + i;
        Wte[(size_t)n * K + k0 + threadIdx.x] = t[threadIdx.x][threadIdx.y + i];
    }
}

// ---------------- tf32 tensor GEMM, cp.async double-buffered ----------------
// C[128x128 tile] = act(A @ Wt[e]^T + bias[e])
// A: [rows,K] K-contig, Wt: [E][Ntot][K] K-contig, bias: [E][Ntot], C stride Ntot.
#define BK 16
#define TS 20          // smem row stride (floats): conflict-free frags, 16B-aligned rows (80B)

__global__ void __launch_bounds__(256, 2)
k_gemm_mma(const float* __restrict__ Abase, const float* __restrict__ Wt,
           const float* __restrict__ Ball, float* __restrict__ C,
           int Ntot, int K, int act) {
    int tile_m = blockIdx.y, tile_n = blockIdx.x;
    int e = g_tile2e[tile_m];
    if (e < 0) return;

    const float* A = Abase + (size_t)tile_m * 128 * K;
    const float* B = Wt + (size_t)e * Ntot * K + (size_t)tile_n * 128 * K;

    __shared__ uint32_t As[2][128][TS];   // [m][k], 10.2KB each
    __shared__ uint32_t Bs[2][128][TS];   // [n][k]

    int tid = threadIdx.x, lane = tid & 31, wid = tid >> 5;
    int wm = wid & 1, wn = wid >> 1;      // warp tile 64(m) x 32(n)
    int grp = lane >> 2, thr = lane & 3;

    // staging role: thread q covers (row = q>>1, seg = q&1) twice -> 4 cp16 per thread
    int srow = tid >> 1;                  // 0..127
    int sseg = (tid & 1) << 1;            // 0 or 2 (two 16B segs each)
    uint32_t a_dst0 = smem_u32(&As[0][srow][sseg * 4]);
    uint32_t b_dst0 = smem_u32(&Bs[0][srow][sseg * 4]);
    const size_t BUFB = 128 * TS * 4;     // bytes per buffer

    float acc[4][4][4];
    #pragma unroll
    for (int mf = 0; mf < 4; mf++)
        #pragma unroll
        for (int nf = 0; nf < 4; nf++)
            #pragma unroll
            for (int c = 0; c < 4; c++) acc[mf][nf][c] = 0.f;

    int nk = K / BK;

    // prologue: stage chunk 0 into buf 0
    {
        const float* as = A + (size_t)srow * K + sseg * 4;
        const float* bs = B + (size_t)srow * K + sseg * 4;
        cp16(a_dst0, as);            cp16(a_dst0 + 16, as + 4);
        cp16(b_dst0, bs);            cp16(b_dst0 + 16, bs + 4);
        CP_COMMIT();
    }

    for (int kc = 0; kc < nk; kc++) {
        int nbuf = (kc + 1) & 1;
        if (kc + 1 < nk) {           // stage next chunk
            int k0 = (kc + 1) * BK;
            const float* as = A + (size_t)srow * K + k0 + sseg * 4;
            const float* bs = B + (size_t)srow * K + k0 + sseg * 4;
            uint32_t ad = a_dst0 + (uint32_t)(nbuf * BUFB);
            uint32_t bd = b_dst0 + (uint32_t)(nbuf * BUFB);
            cp16(ad, as);            cp16(ad + 16, as + 4);
            cp16(bd, bs);            cp16(bd + 16, bs + 4);
        }
        CP_COMMIT();
        CP_WAIT1();                  // chunk kc landed
        __syncthreads();

        int buf = kc & 1;
        #pragma unroll
        for (int ks = 0; ks < BK; ks += 8) {
            uint32_t af[4][4], bf[4][2];
            #pragma unroll
            for (int mf = 0; mf < 4; mf++) {
                int m0 = wm * 64 + mf * 16 + grp;
                af[mf][0] = As[buf][m0    ][ks + thr    ];
                af[mf][1] = As[buf][m0 + 8][ks + thr    ];
                af[mf][2] = As[buf][m0    ][ks + thr + 4];
                af[mf][3] = As[buf][m0 + 8][ks + thr + 4];
            }
            #pragma unroll
            for (int nf = 0; nf < 4; nf++) {
                int n0 = wn * 32 + nf * 8 + grp;
                bf[nf][0] = Bs[buf][n0][ks + thr    ];
                bf[nf][1] = Bs[buf][n0][ks + thr + 4];
            }
            #pragma unroll
            for (int mf = 0; mf < 4; mf++)
                #pragma unroll
                for (int nf = 0; nf < 4; nf++)
                    mma16n8k8(acc[mf][nf], af[mf][0], af[mf][1], af[mf][2], af[mf][3],
                              bf[nf][0], bf[nf][1]);
        }
        __syncthreads();             // all reads of buf done before it is re-staged
    }

    // epilogue: bias (+ SiLU + rna), direct float2 stores
    const float* bias = Ball + (size_t)e * Ntot + (size_t)tile_n * 128;
    float* Cb = C + (size_t)tile_m * 128 * Ntot + (size_t)tile_n * 128;
    #pragma unroll
    for (int mf = 0; mf < 4; mf++) {
        #pragma unroll
        for (int nf = 0; nf < 4; nf++) {
            int row = wm * 64 + mf * 16 + grp;
            int col = wn * 32 + nf * 8 + thr * 2;
            float b0 = bias[col], b1 = bias[col + 1];
            float v00 = acc[mf][nf][0] + b0, v01 = acc[mf][nf][1] + b1;
            float v10 = acc[mf][nf][2] + b0, v11 = acc[mf][nf][3] + b1;
            if (act) {
                v00 = tf32r(v00 / (1.f + __expf(-v00)));
                v01 = tf32r(v01 / (1.f + __expf(-v01)));
                v10 = tf32r(v10 / (1.f + __expf(-v10)));
                v11 = tf32r(v11 / (1.f + __expf(-v11)));
            }
            *(float2*)(Cb + (size_t)row * Ntot + col)       = make_float2(v00, v01);
            *(float2*)(Cb + (size_t)(row + 8) * Ntot + col) = make_float2(v10, v11);
        }
    }
}

// ---------------- combine ----------------
__global__ void k_combine(float* __restrict__ out, int D) {
    int t = blockIdx.x;
    int rows[SLOT_MAX]; float ws[SLOT_MAX];
    #pragma unroll
    for (int s = 0; s < SLOT_MAX; s++) { rows[s] = g_pos[t*SLOT_MAX+s]; ws[s] = g_wts[t*SLOT_MAX+s]; }
    float4* dst = (float4*)(out + (size_t)t * D);
    for (int c = threadIdx.x; c < (D >> 2); c += blockDim.x) {
        float4 a = make_float4(0.f, 0.f, 0.f, 0.f);
        #pragma unroll
        for (int s = 0; s < SLOT_MAX; s++) {
            if (rows[s] < 0) continue;
            const float4 v = ((const float4*)(g_O + (size_t)rows[s] * D))[c];
            a.x = fmaf(ws[s], v.x, a.x); a.y = fmaf(ws[s], v.y, a.y);
            a.z = fmaf(ws[s], v.z, a.z); a.w = fmaf(ws[s], v.w, a.w);
        }
        dst[c] = a;
    }
}

// ---------------- launch ----------------
extern "C" void kernel_launch(void* const* d_in, const int* in_sizes, int n_in,
                              void* d_out, int out_size) {
    const float* x    = (const float*)d_in[0];
    const float* gw   = (const float*)d_in[1];
    const float* gb   = (const float*)d_in[2];
    const float* w1   = (const float*)d_in[3];
    const float* b1   = (const float*)d_in[4];
    const float* w2   = (const float*)d_in[5];
    const float* b2   = (const float*)d_in[6];
    const int*   topk = (n_in > 7) ? (const int*)d_in[7] : nullptr;
    float* out = (float*)d_out;

    const int E = in_sizes[2];
    const int D = in_sizes[1] / E;
    const int F = in_sizes[4] / E;
    const int T = in_sizes[0] / D;

    float *Xg = nullptr, *H = nullptr, *O = nullptr, *W1t = nullptr, *W2t = nullptr;
    cudaGetSymbolAddress((void**)&Xg,  g_Xg);
    cudaGetSymbolAddress((void**)&H,   g_H);
    cudaGetSymbolAddress((void**)&O,   g_O);
    cudaGetSymbolAddress((void**)&W1t, g_W1t);
    cudaGetSymbolAddress((void**)&W2t, g_W2t);

    k_init<<<(RPAD_MAX + 255) / 256, 256>>>();
    k_router<<<T, 256>>>(x, gw, gb, topk, D, E);
    k_scan<<<1, 32>>>(E);
    k_assign<<<(T * SLOT_MAX + 255) / 256, 256>>>(T);
    k_gather<<<RPAD_MAX, 256>>>(x, D);

    dim3 bt(32, 8);
    k_wconv<<<dim3(F / 32, D / 32, E), bt>>>(w1, W1t, D, F);   // [E][D][F] -> [E][F][D]
    k_wconv<<<dim3(D / 32, F / 32, E), bt>>>(w2, W2t, F, D);   // [E][F][D] -> [E][D][F]

    k_gemm_mma<<<dim3(F / 128, TILES_MAX), 256>>>(Xg, W1t, b1, H, F, D, 1);
    k_gemm_mma<<<dim3(D / 128, TILES_MAX), 256>>>(H, W2t, b2, O, D, F, 0);

    k_combine<<<T, 256>>>(out, D);
}

// round 6
// speedup vs baseline: 3.0929x; 1.3028x over previous
#include <cuda_runtime.h>
#include <cuda_bf16.h>
#include <math.h>
#include <stdint.h>

// ---------------- problem-size maxima (fixed instance: T=4096,D=1024,F=4096,E=8,k=2)
#define T_MAX    4096
#define E_MAX    8
#define SLOT_MAX 2
#define D_MAX    1024
#define F_MAX    4096
#define RPAD_MAX (T_MAX * SLOT_MAX + E_MAX * 128)   // 9216
#define TILES_MAX (RPAD_MAX / 128)                  // 72

// ---------------- device scratch (static: no allocation anywhere)
__device__ float g_Xg [(size_t)RPAD_MAX * D_MAX];   // gathered tokens (tf32-rounded)
__device__ float g_H  [(size_t)RPAD_MAX * F_MAX];   // hidden (tf32-rounded)
__device__ float g_O  [(size_t)RPAD_MAX * D_MAX];   // expert outputs (fp32)
__device__ int   g_sel [T_MAX * SLOT_MAX];
__device__ float g_wts [T_MAX * SLOT_MAX];
__device__ int   g_pos [T_MAX * SLOT_MAX];
__device__ int   g_count [E_MAX];
__device__ int   g_cursor[E_MAX];
__device__ int   g_off   [E_MAX + 1];
__device__ int   g_tile2e[TILES_MAX];
__device__ int   g_row2tok[RPAD_MAX];

// ---------------- helpers ----------------
__device__ __forceinline__ float tf32r(float x) {   // round-to-nearest tf32
    uint32_t u;
    asm("cvt.rna.tf32.f32 %0, %1;" : "=r"(u) : "f"(x));
    return __uint_as_float(u);
}
__device__ __forceinline__ uint32_t tf32r_u(uint32_t x) {   // same, on raw bits
    uint32_t u;
    asm("cvt.rna.tf32.f32 %0, %1;" : "=r"(u) : "f"(__uint_as_float(x)));
    return u;
}
__device__ __forceinline__ uint32_t smem_u32(const void* p) {
    uint32_t a;
    asm("{ .reg .u64 t; cvta.to.shared.u64 t, %1; cvt.u32.u64 %0, t; }" : "=r"(a) : "l"(p));
    return a;
}
__device__ __forceinline__ void cp16(uint32_t dst, const void* src) {
    asm volatile("cp.async.cg.shared.global [%0], [%1], 16;" :: "r"(dst), "l"(src));
}
#define CP_COMMIT() asm volatile("cp.async.commit_group;" ::: "memory")
#define CP_WAIT1()  asm volatile("cp.async.wait_group 1;" ::: "memory")

// warp-level tensor op, baseline target (compiles for compute_103, runs on tensor pipe)
__device__ __forceinline__ void mma16n8k8(float c[4],
                                          uint32_t a0, uint32_t a1, uint32_t a2, uint32_t a3,
                                          uint32_t b0, uint32_t b1) {
    asm volatile(
        "mma.sync.aligned.m16n8k8.row.col.f32.tf32.tf32.f32 "
        "{%0,%1,%2,%3}, {%4,%5,%6,%7}, {%8,%9}, {%0,%1,%2,%3};"
        : "+f"(c[0]), "+f"(c[1]), "+f"(c[2]), "+f"(c[3])
        : "r"(a0), "r"(a1), "r"(a2), "r"(a3), "r"(b0), "r"(b1));
}

// ---------------- init ----------------
__global__ void k_init() {
    int i = blockIdx.x * blockDim.x + threadIdx.x;
    if (i < RPAD_MAX)  g_row2tok[i] = -1;
    if (i < TILES_MAX) g_tile2e[i]  = -1;
    if (i < E_MAX)   { g_count[i] = 0; g_cursor[i] = 0; }
}

// ---------------- router ----------------
__global__ void k_router(const float* __restrict__ x, const float* __restrict__ gw,
                         const float* __restrict__ gb, const int* __restrict__ topk_p,
                         int D, int E) {
    int t = blockIdx.x;
    float acc[E_MAX];
    #pragma unroll
    for (int e = 0; e < E_MAX; e++) acc[e] = 0.f;
    const float* xr = x + (size_t)t * D;
    for (int d = threadIdx.x; d < D; d += blockDim.x) {
        float xv = xr[d];
        for (int e = 0; e < E; e++) acc[e] += xv * gw[(size_t)e * D + d];
    }
    __shared__ float sred[E_MAX][8];
    int lane = threadIdx.x & 31, wid = threadIdx.x >> 5;
    for (int e = 0; e < E; e++) {
        float v = acc[e];
        #pragma unroll
        for (int o = 16; o > 0; o >>= 1) v += __shfl_down_sync(0xffffffffu, v, o);
        if (lane == 0) sred[e][wid] = v;
    }
    __syncthreads();
    if (threadIdx.x == 0) {
        int nw = blockDim.x >> 5;
        float logit[E_MAX], mx = -1e30f;
        for (int e = 0; e < E; e++) {
            float s = gb[e];
            for (int w = 0; w < nw; w++) s += sred[e][w];
            logit[e] = s; mx = fmaxf(mx, s);
        }
        float p[E_MAX], Z = 0.f;
        for (int e = 0; e < E; e++) { p[e] = expf(logit[e] - mx); Z += p[e]; }
        float invZ = 1.f / Z;
        for (int e = 0; e < E; e++) p[e] *= invZ;

        int k = topk_p ? *topk_p : 2;
        if (k > SLOT_MAX) k = SLOT_MAX;
        if (k < 1) k = 1;
        bool used[E_MAX];
        for (int e = 0; e < E; e++) used[e] = false;
        float wsum = 0.f;
        int sels[SLOT_MAX]; float wv[SLOT_MAX];
        for (int s = 0; s < k; s++) {
            int best = 0; float bv = -1.f;
            for (int e = 0; e < E; e++)
                if (!used[e] && p[e] > bv) { bv = p[e]; best = e; }  // strict > => lowest idx on tie
            used[best] = true;
            sels[s] = best; wv[s] = bv; wsum += bv;
            atomicAdd(&g_count[best], 1);
        }
        float inv = 1.f / wsum;
        for (int s = 0; s < k; s++) { g_sel[t*SLOT_MAX+s] = sels[s]; g_wts[t*SLOT_MAX+s] = wv[s]*inv; }
        for (int s = k; s < SLOT_MAX; s++) { g_sel[t*SLOT_MAX+s] = -1; g_wts[t*SLOT_MAX+s] = 0.f; }
    }
}

// ---------------- scan ----------------
__global__ void k_scan(int E) {
    if (threadIdx.x != 0 || blockIdx.x != 0) return;
    int off = 0;
    for (int e = 0; e < E; e++) {
        g_off[e] = off;
        int tiles = (g_count[e] + 127) >> 7;
        for (int i = 0; i < tiles; i++) g_tile2e[(off >> 7) + i] = e;
        off += tiles << 7;
    }
    g_off[E] = off;
}

// ---------------- assign ----------------
__global__ void k_assign(int T) {
    int idx = blockIdx.x * blockDim.x + threadIdx.x;
    if (idx >= T * SLOT_MAX) return;
    int t = idx / SLOT_MAX, s = idx % SLOT_MAX;
    int e = g_sel[t * SLOT_MAX + s];
    if (e < 0) { g_pos[t * SLOT_MAX + s] = -1; return; }
    int pos = atomicAdd(&g_cursor[e], 1);
    int row = g_off[e] + pos;
    g_row2tok[row] = t;
    g_pos[t * SLOT_MAX + s] = row;
}

// ---------------- gather (+ tf32 rna rounding) ----------------
__global__ void k_gather(const float* __restrict__ x, int D) {
    int row = blockIdx.x;
    int tok = g_row2tok[row];
    float4* dst = (float4*)(g_Xg + (size_t)row * D);
    if (tok >= 0) {
        const float4* src = (const float4*)(x + (size_t)tok * D);
        for (int c = threadIdx.x; c < (D >> 2); c += blockDim.x) {
            float4 v = src[c];
            v.x = tf32r(v.x); v.y = tf32r(v.y); v.z = tf32r(v.z); v.w = tf32r(v.w);
            dst[c] = v;
        }
    } else {
        float4 z = make_float4(0.f, 0.f, 0.f, 0.f);
        for (int c = threadIdx.x; c < (D >> 2); c += blockDim.x) dst[c] = z;
    }
}

// ---------------- tf32 tensor GEMM, cp.async 3-buffer pipeline ----------------
// C[128x128 tile] = act(A @ W[e] + bias[e])
// A: [rows,K] K-contig (tf32-pre-rounded), W: [E][K][Ntot] NATIVE layout (n-contig,
// raw fp32 — rounded to tf32 in registers), bias: [E][Ntot], C row stride Ntot.
#define BK  16
#define TSA 20     // A smem row stride (floats): frag lanes grp*20+thr -> conflict-free
#define TSB 136    // B smem row stride (floats): frag lanes thr*136+grp = thr*8+grp -> conflict-free

__global__ void __launch_bounds__(256, 2)
k_gemm_mma(const float* __restrict__ Abase, const float* __restrict__ W,
           const float* __restrict__ Ball, float* __restrict__ C,
           int Ntot, int K, int act) {
    int tile_m = blockIdx.y, tile_n = blockIdx.x;
    int e = g_tile2e[tile_m];
    if (e < 0) return;

    const float* A = Abase + (size_t)tile_m * 128 * K;
    const float* B = W + (size_t)e * K * Ntot + (size_t)tile_n * 128;   // [k][n], n-contig

    __shared__ uint32_t As[3][128][TSA];   // [m][k]  10.24KB each
    __shared__ uint32_t Bs[3][16][TSB];    // [k][n]   8.70KB each

    int tid = threadIdx.x, lane = tid & 31, wid = tid >> 5;
    int wm = wid & 1, wn = wid >> 1;       // warp tile 64(m) x 32(n)
    int grp = lane >> 2, thr = lane & 3;

    // staging roles
    int arow = tid >> 1;                   // 0..127
    int aseg = (tid & 1) << 1;             // {0,2}: two 16B segs per thread
    int brow = tid >> 4;                   // 0..15
    int bseg = (tid & 15) << 1;            // {0..30}: two 16B segs per thread
    uint32_t a_s0 = smem_u32(&As[0][arow][aseg * 4]);
    uint32_t b_s0 = smem_u32(&Bs[0][brow][bseg * 4]);
    const uint32_t ABUF = 128 * TSA * 4;   // bytes per A buffer
    const uint32_t BBUF = 16 * TSB * 4;    // bytes per B buffer

    const float* aptr = A + (size_t)arow * K + aseg * 4;
    const float* bptr = B + (size_t)brow * Ntot + bseg * 4;
    const size_t bstep = (size_t)BK * Ntot;

    float acc[4][4][4];
    #pragma unroll
    for (int mf = 0; mf < 4; mf++)
        #pragma unroll
        for (int nf = 0; nf < 4; nf++)
            #pragma unroll
            for (int c = 0; c < 4; c++) acc[mf][nf][c] = 0.f;

    int nk = K / BK;

    // prologue: stage chunk 0 -> buf 0
    cp16(a_s0,      aptr);     cp16(a_s0 + 16, aptr + 4);
    cp16(b_s0,      bptr);     cp16(b_s0 + 16, bptr + 4);
    CP_COMMIT();

    int buf = 0, nbuf = 1;
    for (int kc = 0; kc < nk; kc++) {
        if (kc + 1 < nk) {                 // stage chunk kc+1 one-ahead
            const float* ap = aptr + (kc + 1) * BK;
            const float* bp = bptr + (size_t)(kc + 1) * bstep;
            uint32_t ad = a_s0 + nbuf * ABUF;
            uint32_t bd = b_s0 + nbuf * BBUF;
            cp16(ad, ap);      cp16(ad + 16, ap + 4);
            cp16(bd, bp);      cp16(bd + 16, bp + 4);
        }
        CP_COMMIT();
        CP_WAIT1();                        // chunk kc landed
        __syncthreads();                   // single barrier per chunk (3 buffers => safe)

        #pragma unroll
        for (int ks = 0; ks < BK; ks += 8) {
            uint32_t af[4][4], bf[4][2];
            #pragma unroll
            for (int mf = 0; mf < 4; mf++) {
                int m0 = wm * 64 + mf * 16 + grp;
                af[mf][0] = As[buf][m0    ][ks + thr    ];
                af[mf][1] = As[buf][m0 + 8][ks + thr    ];
                af[mf][2] = As[buf][m0    ][ks + thr + 4];
                af[mf][3] = As[buf][m0 + 8][ks + thr + 4];
            }
            #pragma unroll
            for (int nf = 0; nf < 4; nf++) {   // weights: rna-round in registers
                int n0 = wn * 32 + nf * 8 + grp;
                bf[nf][0] = tf32r_u(Bs[buf][ks + thr    ][n0]);
                bf[nf][1] = tf32r_u(Bs[buf][ks + thr + 4][n0]);
            }
            #pragma unroll
            for (int mf = 0; mf < 4; mf++)
                #pragma unroll
                for (int nf = 0; nf < 4; nf++)
                    mma16n8k8(acc[mf][nf], af[mf][0], af[mf][1], af[mf][2], af[mf][3],
                              bf[nf][0], bf[nf][1]);
        }
        buf = nbuf;
        nbuf = nbuf + 1; if (nbuf == 3) nbuf = 0;
    }

    // epilogue: bias (+ SiLU + rna), direct float2 stores
    const float* bias = Ball + (size_t)e * Ntot + (size_t)tile_n * 128;
    float* Cb = C + (size_t)tile_m * 128 * Ntot + (size_t)tile_n * 128;
    #pragma unroll
    for (int mf = 0; mf < 4; mf++) {
        #pragma unroll
        for (int nf = 0; nf < 4; nf++) {
            int row = wm * 64 + mf * 16 + grp;
            int col = wn * 32 + nf * 8 + thr * 2;
            float b0 = bias[col], b1 = bias[col + 1];
            float v00 = acc[mf][nf][0] + b0, v01 = acc[mf][nf][1] + b1;
            float v10 = acc[mf][nf][2] + b0, v11 = acc[mf][nf][3] + b1;
            if (act) {
                v00 = tf32r(v00 / (1.f + __expf(-v00)));
                v01 = tf32r(v01 / (1.f + __expf(-v01)));
                v10 = tf32r(v10 / (1.f + __expf(-v10)));
                v11 = tf32r(v11 / (1.f + __expf(-v11)));
            }
            *(float2*)(Cb + (size_t)row * Ntot + col)       = make_float2(v00, v01);
            *(float2*)(Cb + (size_t)(row + 8) * Ntot + col) = make_float2(v10, v11);
        }
    }
}

// ---------------- combine ----------------
__global__ void k_combine(float* __restrict__ out, int D) {
    int t = blockIdx.x;
    int rows[SLOT_MAX]; float ws[SLOT_MAX];
    #pragma unroll
    for (int s = 0; s < SLOT_MAX; s++) { rows[s] = g_pos[t*SLOT_MAX+s]; ws[s] = g_wts[t*SLOT_MAX+s]; }
    float4* dst = (float4*)(out + (size_t)t * D);
    for (int c = threadIdx.x; c < (D >> 2); c += blockDim.x) {
        float4 a = make_float4(0.f, 0.f, 0.f, 0.f);
        #pragma unroll
        for (int s = 0; s < SLOT_MAX; s++) {
            if (rows[s] < 0) continue;
            const float4 v = ((const float4*)(g_O + (size_t)rows[s] * D))[c];
            a.x = fmaf(ws[s], v.x, a.x); a.y = fmaf(ws[s], v.y, a.y);
            a.z = fmaf(ws[s], v.z, a.z); a.w = fmaf(ws[s], v.w, a.w);
        }
        dst[c] = a;
    }
}

// ---------------- launch ----------------
extern "C" void kernel_launch(void* const* d_in, const int* in_sizes, int n_in,
                              void* d_out, int out_size) {
    const float* x    = (const float*)d_in[0];
    const float* gw   = (const float*)d_in[1];
    const float* gb   = (const float*)d_in[2];
    const float* w1   = (const float*)d_in[3];
    const float* b1   = (const float*)d_in[4];
    const float* w2   = (const float*)d_in[5];
    const float* b2   = (const float*)d_in[6];
    const int*   topk = (n_in > 7) ? (const int*)d_in[7] : nullptr;
    float* out = (float*)d_out;

    const int E = in_sizes[2];
    const int D = in_sizes[1] / E;
    const int F = in_sizes[4] / E;
    const int T = in_sizes[0] / D;

    float *Xg = nullptr, *H = nullptr, *O = nullptr;
    cudaGetSymbolAddress((void**)&Xg, g_Xg);
    cudaGetSymbolAddress((void**)&H,  g_H);
    cudaGetSymbolAddress((void**)&O,  g_O);

    k_init<<<(RPAD_MAX + 255) / 256, 256>>>();
    k_router<<<T, 256>>>(x, gw, gb, topk, D, E);
    k_scan<<<1, 32>>>(E);
    k_assign<<<(T * SLOT_MAX + 255) / 256, 256>>>(T);
    k_gather<<<RPAD_MAX, 256>>>(x, D);

    // weights consumed in NATIVE [E][K][N] layout — no transpose pass
    k_gemm_mma<<<dim3(F / 128, TILES_MAX), 256>>>(Xg, w1, b1, H, F, D, 1);
    k_gemm_mma<<<dim3(D / 128, TILES_MAX), 256>>>(H, w2, b2, O, D, F, 0);

    k_combine<<<T, 256>>>(out, D);
}